// round 1
// baseline (speedup 1.0000x reference)
#include <cuda_runtime.h>
#include <math.h>

#define NMAX 50000
#define EPS_LN 1e-5f

// Scratch: P = x @ sp_w1[0:64,:], Q = x @ sp_w1[64:128,:]   (each [N,256])
__device__ float g_P[(size_t)NMAX * 256];
__device__ float g_Q[(size_t)NMAX * 256];

__device__ __forceinline__ float wredsum(float v) {
#pragma unroll
    for (int o = 16; o > 0; o >>= 1) v += __shfl_xor_sync(0xffffffffu, v, o);
    return v;
}

__device__ __forceinline__ float gelu_exact(float v) {
    // jax.nn.gelu(approximate=False) == x * Phi(x)
    return v * normcdff(v);
}

// ============================================================================
// K1: P,Q = x @ W_top, x @ W_bot.  TILE=16 nodes, 128 threads, 2 cols/thread,
// both halves per thread -> 16 FMA per LDS.128 (crossbar-balanced).
// ============================================================================
__global__ __launch_bounds__(128) void k_pq(const float* __restrict__ x,
                                            const float* __restrict__ w,  // [128,256]
                                            int N) {
    __shared__ float xs[16][64];
    const int t = threadIdx.x;
    const int n0 = blockIdx.x * 16;

    {
        float4* xs4 = reinterpret_cast<float4*>(&xs[0][0]);
        const float4* x4 = reinterpret_cast<const float4*>(x);
#pragma unroll
        for (int i = t; i < 256; i += 128) {
            int node = n0 + (i >> 4);
            float4 v = make_float4(0.f, 0.f, 0.f, 0.f);
            if (node < N) v = x4[(size_t)node * 16 + (i & 15)];
            xs4[i] = v;
        }
    }
    __syncthreads();

    float aP0[16], aP1[16], aQ0[16], aQ1[16];
#pragma unroll
    for (int m = 0; m < 16; m++) { aP0[m] = 0.f; aP1[m] = 0.f; aQ0[m] = 0.f; aQ1[m] = 0.f; }

    const int c0 = t, c1 = t + 128;
#pragma unroll 2
    for (int k4 = 0; k4 < 16; k4++) {
        float wp0[4], wp1[4], wq0[4], wq1[4];
#pragma unroll
        for (int j = 0; j < 4; j++) {
            int k = k4 * 4 + j;
            wp0[j] = w[k * 256 + c0];
            wp1[j] = w[k * 256 + c1];
            wq0[j] = w[(64 + k) * 256 + c0];
            wq1[j] = w[(64 + k) * 256 + c1];
        }
#pragma unroll
        for (int m = 0; m < 16; m++) {
            float4 xv = *reinterpret_cast<const float4*>(&xs[m][k4 * 4]);
            float xa[4] = {xv.x, xv.y, xv.z, xv.w};
#pragma unroll
            for (int j = 0; j < 4; j++) {
                aP0[m] = fmaf(xa[j], wp0[j], aP0[m]);
                aP1[m] = fmaf(xa[j], wp1[j], aP1[m]);
                aQ0[m] = fmaf(xa[j], wq0[j], aQ0[m]);
                aQ1[m] = fmaf(xa[j], wq1[j], aQ1[m]);
            }
        }
    }

#pragma unroll
    for (int m = 0; m < 16; m++) {
        int n = n0 + m;
        if (n >= N) break;
        g_P[(size_t)n * 256 + c0] = aP0[m];
        g_P[(size_t)n * 256 + c1] = aP1[m];
        g_Q[(size_t)n * 256 + c0] = aQ0[m];
        g_Q[(size_t)n * 256 + c1] = aQ1[m];
    }
}

// ============================================================================
// K2: per-edge  out = GELU(LN(P[row]+Q[col]+b1)) . w2 + b2
// One warp per edge, 16 edges per warp; params live in registers.
// ============================================================================
#define EPW 16
__global__ __launch_bounds__(256) void k_edge(const int* __restrict__ ei, int E,
                                              const float* __restrict__ b1,
                                              const float* __restrict__ gm,
                                              const float* __restrict__ bt,
                                              const float* __restrict__ w2,
                                              const float* __restrict__ b2p,
                                              float* __restrict__ out) {
    const int lane = threadIdx.x & 31;
    const long warp = (long)blockIdx.x * (blockDim.x >> 5) + (threadIdx.x >> 5);

    // each lane owns elements [lane*4 .. lane*4+3] and [128+lane*4 .. +3]
    const float4* b1v = reinterpret_cast<const float4*>(b1);
    const float4* gmv = reinterpret_cast<const float4*>(gm);
    const float4* btv = reinterpret_cast<const float4*>(bt);
    const float4* w2v = reinterpret_cast<const float4*>(w2);
    float4 rb1a = b1v[lane], rb1b = b1v[32 + lane];
    float4 rga = gmv[lane], rgb = gmv[32 + lane];
    float4 rba = btv[lane], rbb = btv[32 + lane];
    float4 rwa = w2v[lane], rwb = w2v[32 + lane];
    float ga[8] = {rga.x, rga.y, rga.z, rga.w, rgb.x, rgb.y, rgb.z, rgb.w};
    float ba[8] = {rba.x, rba.y, rba.z, rba.w, rbb.x, rbb.y, rbb.z, rbb.w};
    float wa[8] = {rwa.x, rwa.y, rwa.z, rwa.w, rwb.x, rwb.y, rwb.z, rwb.w};
    float bb[8] = {rb1a.x, rb1a.y, rb1a.z, rb1a.w, rb1b.x, rb1b.y, rb1b.z, rb1b.w};
    const float b2 = __ldg(b2p);

    const float4* P4 = reinterpret_cast<const float4*>(g_P);
    const float4* Q4 = reinterpret_cast<const float4*>(g_Q);

    long e0 = warp * EPW;
    for (int i = 0; i < EPW; i++) {
        long e = e0 + i;
        if (e >= E) return;
        int r = __ldg(&ei[e]);
        int c = __ldg(&ei[(long)E + e]);

        float4 pa = P4[(size_t)r * 64 + lane];
        float4 pb = P4[(size_t)r * 64 + 32 + lane];
        float4 qa = Q4[(size_t)c * 64 + lane];
        float4 qb = Q4[(size_t)c * 64 + 32 + lane];

        float s[8];
        s[0] = pa.x + qa.x + bb[0];
        s[1] = pa.y + qa.y + bb[1];
        s[2] = pa.z + qa.z + bb[2];
        s[3] = pa.w + qa.w + bb[3];
        s[4] = pb.x + qb.x + bb[4];
        s[5] = pb.y + qb.y + bb[5];
        s[6] = pb.z + qb.z + bb[6];
        s[7] = pb.w + qb.w + bb[7];

        float sum = 0.f, sq = 0.f;
#pragma unroll
        for (int j = 0; j < 8; j++) { sum += s[j]; sq = fmaf(s[j], s[j], sq); }
        sum = wredsum(sum);
        sq = wredsum(sq);
        float mean = sum * (1.f / 256.f);
        float var = sq * (1.f / 256.f) - mean * mean;
        float rstd = rsqrtf(var + EPS_LN);

        float acc = 0.f;
#pragma unroll
        for (int j = 0; j < 8; j++) {
            float u = fmaf((s[j] - mean) * rstd, ga[j], ba[j]);
            acc = fmaf(gelu_exact(u), wa[j], acc);
        }
        acc = wredsum(acc);
        if (lane == 0) out[e] = acc + b2;
    }
}

// ============================================================================
// K3: fr branch  x[64] -> Linear(128) -> LN -> GELU -> Linear(64)
// 64 threads, 16 nodes/block. Fully fused through shared memory.
// ============================================================================
__global__ __launch_bounds__(64) void k_fr(const float* __restrict__ x,
                                           const float* __restrict__ w1,  // [64,128]
                                           const float* __restrict__ b1,
                                           const float* __restrict__ gm,
                                           const float* __restrict__ bt,
                                           const float* __restrict__ w2,  // [128,64]
                                           const float* __restrict__ b2,
                                           float* __restrict__ out, int N) {
    __shared__ float xs[16][64];
    __shared__ float hs[16][128];
    const int t = threadIdx.x;
    const int n0 = blockIdx.x * 16;

    {
        float4* xs4 = reinterpret_cast<float4*>(&xs[0][0]);
        const float4* x4 = reinterpret_cast<const float4*>(x);
#pragma unroll
        for (int i = t; i < 256; i += 64) {
            int node = n0 + (i >> 4);
            float4 v = make_float4(0.f, 0.f, 0.f, 0.f);
            if (node < N) v = x4[(size_t)node * 16 + (i & 15)];
            xs4[i] = v;
        }
    }
    __syncthreads();

    // GEMM1: 2 cols/thread
    float a0[16], a1[16];
#pragma unroll
    for (int m = 0; m < 16; m++) { a0[m] = 0.f; a1[m] = 0.f; }
    const int c0 = t, c1 = t + 64;
#pragma unroll 2
    for (int k4 = 0; k4 < 16; k4++) {
        float wr0[4], wr1[4];
#pragma unroll
        for (int j = 0; j < 4; j++) {
            int k = k4 * 4 + j;
            wr0[j] = w1[k * 128 + c0];
            wr1[j] = w1[k * 128 + c1];
        }
#pragma unroll
        for (int m = 0; m < 16; m++) {
            float4 xv = *reinterpret_cast<const float4*>(&xs[m][k4 * 4]);
            float xa[4] = {xv.x, xv.y, xv.z, xv.w};
#pragma unroll
            for (int j = 0; j < 4; j++) {
                a0[m] = fmaf(xa[j], wr0[j], a0[m]);
                a1[m] = fmaf(xa[j], wr1[j], a1[m]);
            }
        }
    }
    {
        float bb0 = b1[c0], bb1 = b1[c1];
#pragma unroll
        for (int m = 0; m < 16; m++) { hs[m][c0] = a0[m] + bb0; hs[m][c1] = a1[m] + bb1; }
    }
    __syncthreads();

    // LN + GELU (2 warps x 8 nodes), 4 elems/lane
    {
        const int warp = t >> 5, lane = t & 31;
        float rg[4], rb[4];
#pragma unroll
        for (int q = 0; q < 4; q++) { rg[q] = gm[lane + 32 * q]; rb[q] = bt[lane + 32 * q]; }
        for (int mm = 0; mm < 8; mm++) {
            int m = warp * 8 + mm;
            float v[4];
            float sum = 0.f, sq = 0.f;
#pragma unroll
            for (int q = 0; q < 4; q++) {
                v[q] = hs[m][lane + 32 * q];
                sum += v[q];
                sq = fmaf(v[q], v[q], sq);
            }
            sum = wredsum(sum);
            sq = wredsum(sq);
            float mean = sum * (1.f / 128.f);
            float var = sq * (1.f / 128.f) - mean * mean;
            float rstd = rsqrtf(var + EPS_LN);
#pragma unroll
            for (int q = 0; q < 4; q++) {
                float u = fmaf((v[q] - mean) * rstd, rg[q], rb[q]);
                hs[m][lane + 32 * q] = gelu_exact(u);
            }
        }
    }
    __syncthreads();

    // GEMM2: thread = (mgroup, 2 outputs)
    {
        const int mg = t >> 5;
        const int o0 = (t & 31) * 2;
        float acc[8][2];
#pragma unroll
        for (int mm = 0; mm < 8; mm++) { acc[mm][0] = 0.f; acc[mm][1] = 0.f; }
#pragma unroll 2
        for (int j4 = 0; j4 < 32; j4++) {
            float2 wv[4];
#pragma unroll
            for (int j = 0; j < 4; j++)
                wv[j] = *reinterpret_cast<const float2*>(&w2[(j4 * 4 + j) * 64 + o0]);
#pragma unroll
            for (int mm = 0; mm < 8; mm++) {
                int m = mg * 8 + mm;
                float4 gv = *reinterpret_cast<const float4*>(&hs[m][j4 * 4]);
                acc[mm][0] = fmaf(gv.x, wv[0].x, acc[mm][0]);
                acc[mm][0] = fmaf(gv.y, wv[1].x, acc[mm][0]);
                acc[mm][0] = fmaf(gv.z, wv[2].x, acc[mm][0]);
                acc[mm][0] = fmaf(gv.w, wv[3].x, acc[mm][0]);
                acc[mm][1] = fmaf(gv.x, wv[0].y, acc[mm][1]);
                acc[mm][1] = fmaf(gv.y, wv[1].y, acc[mm][1]);
                acc[mm][1] = fmaf(gv.z, wv[2].y, acc[mm][1]);
                acc[mm][1] = fmaf(gv.w, wv[3].y, acc[mm][1]);
            }
        }
        float bo0 = b2[o0], bo1 = b2[o0 + 1];
#pragma unroll
        for (int mm = 0; mm < 8; mm++) {
            int n = n0 + mg * 8 + mm;
            if (n < N) {
                out[(size_t)n * 64 + o0] = acc[mm][0] + bo0;
                out[(size_t)n * 64 + o0 + 1] = acc[mm][1] + bo1;
            }
        }
    }
}

// ============================================================================
// K4: ph branch  x[64] -> Linear(256) -> LN -> GELU -> Linear(128)
// ============================================================================
__global__ __launch_bounds__(64) void k_ph(const float* __restrict__ x,
                                           const float* __restrict__ w1,  // [64,256]
                                           const float* __restrict__ b1,
                                           const float* __restrict__ gm,
                                           const float* __restrict__ bt,
                                           const float* __restrict__ w2,  // [256,128]
                                           const float* __restrict__ b2,
                                           float* __restrict__ out, int N) {
    __shared__ float xs[16][64];
    __shared__ float hs[16][256];
    const int t = threadIdx.x;
    const int n0 = blockIdx.x * 16;

    {
        float4* xs4 = reinterpret_cast<float4*>(&xs[0][0]);
        const float4* x4 = reinterpret_cast<const float4*>(x);
#pragma unroll
        for (int i = t; i < 256; i += 64) {
            int node = n0 + (i >> 4);
            float4 v = make_float4(0.f, 0.f, 0.f, 0.f);
            if (node < N) v = x4[(size_t)node * 16 + (i & 15)];
            xs4[i] = v;
        }
    }
    __syncthreads();

    // GEMM1: 4 cols/thread (cols t, t+64, t+128, t+192)
    float a[4][16];
#pragma unroll
    for (int cc = 0; cc < 4; cc++)
#pragma unroll
        for (int m = 0; m < 16; m++) a[cc][m] = 0.f;

#pragma unroll 2
    for (int k4 = 0; k4 < 16; k4++) {
        float wr[4][4];
#pragma unroll
        for (int cc = 0; cc < 4; cc++)
#pragma unroll
            for (int j = 0; j < 4; j++)
                wr[cc][j] = w1[(k4 * 4 + j) * 256 + t + 64 * cc];
#pragma unroll
        for (int m = 0; m < 16; m++) {
            float4 xv = *reinterpret_cast<const float4*>(&xs[m][k4 * 4]);
            float xa[4] = {xv.x, xv.y, xv.z, xv.w};
#pragma unroll
            for (int cc = 0; cc < 4; cc++)
#pragma unroll
                for (int j = 0; j < 4; j++)
                    a[cc][m] = fmaf(xa[j], wr[cc][j], a[cc][m]);
        }
    }
#pragma unroll
    for (int cc = 0; cc < 4; cc++) {
        float bb = b1[t + 64 * cc];
#pragma unroll
        for (int m = 0; m < 16; m++) hs[m][t + 64 * cc] = a[cc][m] + bb;
    }
    __syncthreads();

    // LN + GELU: 8 elems/lane
    {
        const int warp = t >> 5, lane = t & 31;
        float rg[8], rb[8];
#pragma unroll
        for (int q = 0; q < 8; q++) { rg[q] = gm[lane + 32 * q]; rb[q] = bt[lane + 32 * q]; }
        for (int mm = 0; mm < 8; mm++) {
            int m = warp * 8 + mm;
            float v[8];
            float sum = 0.f, sq = 0.f;
#pragma unroll
            for (int q = 0; q < 8; q++) {
                v[q] = hs[m][lane + 32 * q];
                sum += v[q];
                sq = fmaf(v[q], v[q], sq);
            }
            sum = wredsum(sum);
            sq = wredsum(sq);
            float mean = sum * (1.f / 256.f);
            float var = sq * (1.f / 256.f) - mean * mean;
            float rstd = rsqrtf(var + EPS_LN);
#pragma unroll
            for (int q = 0; q < 8; q++) {
                float u = fmaf((v[q] - mean) * rstd, rg[q], rb[q]);
                hs[m][lane + 32 * q] = gelu_exact(u);
            }
        }
    }
    __syncthreads();

    // GEMM2: OUT=128, thread = (mgroup, 4 outputs) -> 16 FMA per LDS.128
    {
        const int mg = t >> 5;
        const int o0 = (t & 31) * 4;
        float acc[8][4];
#pragma unroll
        for (int mm = 0; mm < 8; mm++)
#pragma unroll
            for (int oo = 0; oo < 4; oo++) acc[mm][oo] = 0.f;

#pragma unroll 2
        for (int j4 = 0; j4 < 64; j4++) {
            float4 wv[4];
#pragma unroll
            for (int j = 0; j < 4; j++)
                wv[j] = *reinterpret_cast<const float4*>(&w2[(j4 * 4 + j) * 128 + o0]);
#pragma unroll
            for (int mm = 0; mm < 8; mm++) {
                int m = mg * 8 + mm;
                float4 gv = *reinterpret_cast<const float4*>(&hs[m][j4 * 4]);
                float gvals[4] = {gv.x, gv.y, gv.z, gv.w};
#pragma unroll
                for (int j = 0; j < 4; j++) {
                    acc[mm][0] = fmaf(gvals[j], wv[j].x, acc[mm][0]);
                    acc[mm][1] = fmaf(gvals[j], wv[j].y, acc[mm][1]);
                    acc[mm][2] = fmaf(gvals[j], wv[j].z, acc[mm][2]);
                    acc[mm][3] = fmaf(gvals[j], wv[j].w, acc[mm][3]);
                }
            }
        }
        float4 bo = *reinterpret_cast<const float4*>(&b2[o0]);
#pragma unroll
        for (int mm = 0; mm < 8; mm++) {
            int n = n0 + mg * 8 + mm;
            if (n < N) {
                float4 r;
                r.x = acc[mm][0] + bo.x;
                r.y = acc[mm][1] + bo.y;
                r.z = acc[mm][2] + bo.z;
                r.w = acc[mm][3] + bo.w;
                *reinterpret_cast<float4*>(&out[(size_t)n * 128 + o0]) = r;
            }
        }
    }
}

// ============================================================================
// launch
// ============================================================================
extern "C" void kernel_launch(void* const* d_in, const int* in_sizes, int n_in,
                              void* d_out, int out_size) {
    const float* x = (const float*)d_in[0];
    const int* ei = (const int*)d_in[1];
    const float* sp_w1 = (const float*)d_in[2];
    const float* sp_b1 = (const float*)d_in[3];
    const float* sp_g = (const float*)d_in[4];
    const float* sp_be = (const float*)d_in[5];
    const float* sp_w2 = (const float*)d_in[6];
    const float* sp_b2 = (const float*)d_in[7];
    const float* fr_w1 = (const float*)d_in[8];
    const float* fr_b1 = (const float*)d_in[9];
    const float* fr_g = (const float*)d_in[10];
    const float* fr_be = (const float*)d_in[11];
    const float* fr_w2 = (const float*)d_in[12];
    const float* fr_b2 = (const float*)d_in[13];
    const float* ph_w1 = (const float*)d_in[14];
    const float* ph_b1 = (const float*)d_in[15];
    const float* ph_g = (const float*)d_in[16];
    const float* ph_be = (const float*)d_in[17];
    const float* ph_w2 = (const float*)d_in[18];
    const float* ph_b2 = (const float*)d_in[19];

    const int N = in_sizes[0] / 64;
    const int E = in_sizes[1] / 2;

    float* out_sp = (float*)d_out;             // [E]
    float* out_fr = out_sp + (size_t)E;        // [N,64]
    float* out_ph = out_fr + (size_t)N * 64;   // [N,128]

    int nblk = (N + 15) / 16;
    k_pq<<<nblk, 128>>>(x, sp_w1, N);
    k_fr<<<nblk, 64>>>(x, fr_w1, fr_b1, fr_g, fr_be, fr_w2, fr_b2, out_fr, N);
    k_ph<<<nblk, 64>>>(x, ph_w1, ph_b1, ph_g, ph_be, ph_w2, ph_b2, out_ph, N);

    long warps = ((long)E + EPW - 1) / EPW;
    int eblocks = (int)((warps + 7) / 8);
    k_edge<<<eblocks, 256>>>(ei, E, sp_b1, sp_g, sp_be, sp_w2, sp_b2, out_sp);
}

// round 2
// speedup vs baseline: 1.4973x; 1.4973x over previous
#include <cuda_runtime.h>
#include <math.h>

#define NMAX 50000
#define EPS_LN 1e-5f

// Scratch: P = x @ sp_w1[0:64,:] + sp_b1, Q = x @ sp_w1[64:128,:]   (each [N,256])
__device__ float g_P[(size_t)NMAX * 256];
__device__ float g_Q[(size_t)NMAX * 256];

__device__ __forceinline__ float wredsum(float v) {
#pragma unroll
    for (int o = 16; o > 0; o >>= 1) v += __shfl_xor_sync(0xffffffffu, v, o);
    return v;
}

// Exact-GELU via Abramowitz-Stegun 7.1.26 erf approximation (|err(erf)| <= 1.5e-7).
// ~13 FMA-pipe ops + 2 MUFU, vs ~40 ops for normcdff.
__device__ __forceinline__ float gelu_fast(float u) {
    float z = 0.70710678118654752f * u;
    float az = fabsf(z);
    float t = __fdividef(1.0f, fmaf(0.3275911f, az, 1.0f));
    float poly = t * fmaf(t, fmaf(t, fmaf(t, fmaf(t, 1.061405429f, -1.453152027f),
                                          1.421413741f),
                                  -0.284496736f),
                          0.254829592f);
    float e = __expf(-az * az);
    float erf_az = fmaf(-poly, e, 1.0f);
    float erf_z = copysignf(erf_az, z);
    return 0.5f * u * (1.0f + erf_z);
}

// ============================================================================
// K1: P,Q = x @ W_top (+b1), x @ W_bot.  TILE=16 nodes, 128 threads.
// ============================================================================
__global__ __launch_bounds__(128) void k_pq(const float* __restrict__ x,
                                            const float* __restrict__ w,   // [128,256]
                                            const float* __restrict__ b1,  // [256] folded into P
                                            int N) {
    __shared__ float xs[16][64];
    const int t = threadIdx.x;
    const int n0 = blockIdx.x * 16;

    {
        float4* xs4 = reinterpret_cast<float4*>(&xs[0][0]);
        const float4* x4 = reinterpret_cast<const float4*>(x);
#pragma unroll
        for (int i = t; i < 256; i += 128) {
            int node = n0 + (i >> 4);
            float4 v = make_float4(0.f, 0.f, 0.f, 0.f);
            if (node < N) v = x4[(size_t)node * 16 + (i & 15)];
            xs4[i] = v;
        }
    }
    __syncthreads();

    float aP0[16], aP1[16], aQ0[16], aQ1[16];
#pragma unroll
    for (int m = 0; m < 16; m++) { aP0[m] = 0.f; aP1[m] = 0.f; aQ0[m] = 0.f; aQ1[m] = 0.f; }

    const int c0 = t, c1 = t + 128;
#pragma unroll 2
    for (int k4 = 0; k4 < 16; k4++) {
        float wp0[4], wp1[4], wq0[4], wq1[4];
#pragma unroll
        for (int j = 0; j < 4; j++) {
            int k = k4 * 4 + j;
            wp0[j] = w[k * 256 + c0];
            wp1[j] = w[k * 256 + c1];
            wq0[j] = w[(64 + k) * 256 + c0];
            wq1[j] = w[(64 + k) * 256 + c1];
        }
#pragma unroll
        for (int m = 0; m < 16; m++) {
            float4 xv = *reinterpret_cast<const float4*>(&xs[m][k4 * 4]);
            float xa[4] = {xv.x, xv.y, xv.z, xv.w};
#pragma unroll
            for (int j = 0; j < 4; j++) {
                aP0[m] = fmaf(xa[j], wp0[j], aP0[m]);
                aP1[m] = fmaf(xa[j], wp1[j], aP1[m]);
                aQ0[m] = fmaf(xa[j], wq0[j], aQ0[m]);
                aQ1[m] = fmaf(xa[j], wq1[j], aQ1[m]);
            }
        }
    }

    const float bb0 = b1[c0], bb1 = b1[c1];
#pragma unroll
    for (int m = 0; m < 16; m++) {
        int n = n0 + m;
        if (n >= N) break;
        g_P[(size_t)n * 256 + c0] = aP0[m] + bb0;
        g_P[(size_t)n * 256 + c1] = aP1[m] + bb1;
        g_Q[(size_t)n * 256 + c0] = aQ0[m];
        g_Q[(size_t)n * 256 + c1] = aQ1[m];
    }
}

// ============================================================================
// K2: per-edge  out = GELU(LN(P[row]+Q[col])) . w2 + b2   (b1 folded into P)
// One warp per edge, 16 edges per warp; params live in registers.
// ============================================================================
#define EPW 16
__global__ __launch_bounds__(256) void k_edge(const int* __restrict__ ei, int E,
                                              const float* __restrict__ gm,
                                              const float* __restrict__ bt,
                                              const float* __restrict__ w2,
                                              const float* __restrict__ b2p,
                                              float* __restrict__ out) {
    const int lane = threadIdx.x & 31;
    const long warp = (long)blockIdx.x * (blockDim.x >> 5) + (threadIdx.x >> 5);

    // each lane owns elements [lane*4 .. lane*4+3] and [128+lane*4 .. +3]
    const float4* gmv = reinterpret_cast<const float4*>(gm);
    const float4* btv = reinterpret_cast<const float4*>(bt);
    const float4* w2v = reinterpret_cast<const float4*>(w2);
    float4 rga = gmv[lane], rgb = gmv[32 + lane];
    float4 rba = btv[lane], rbb = btv[32 + lane];
    float4 rwa = w2v[lane], rwb = w2v[32 + lane];
    float ga[8] = {rga.x, rga.y, rga.z, rga.w, rgb.x, rgb.y, rgb.z, rgb.w};
    float ba[8] = {rba.x, rba.y, rba.z, rba.w, rbb.x, rbb.y, rbb.z, rbb.w};
    // 0.5 of GELU folded into w2
    float hw[8] = {0.5f * rwa.x, 0.5f * rwa.y, 0.5f * rwa.z, 0.5f * rwa.w,
                   0.5f * rwb.x, 0.5f * rwb.y, 0.5f * rwb.z, 0.5f * rwb.w};
    const float b2 = __ldg(b2p);

    const float4* P4 = reinterpret_cast<const float4*>(g_P);
    const float4* Q4 = reinterpret_cast<const float4*>(g_Q);

    long e0 = warp * EPW;
    for (int i = 0; i < EPW; i++) {
        long e = e0 + i;
        if (e >= E) return;
        int r = __ldg(&ei[e]);
        int c = __ldg(&ei[(long)E + e]);

        float4 pa = P4[(size_t)r * 64 + lane];
        float4 pb = P4[(size_t)r * 64 + 32 + lane];
        float4 qa = Q4[(size_t)c * 64 + lane];
        float4 qb = Q4[(size_t)c * 64 + 32 + lane];

        float s[8];
        s[0] = pa.x + qa.x;
        s[1] = pa.y + qa.y;
        s[2] = pa.z + qa.z;
        s[3] = pa.w + qa.w;
        s[4] = pb.x + qb.x;
        s[5] = pb.y + qb.y;
        s[6] = pb.z + qb.z;
        s[7] = pb.w + qb.w;

        float sum = 0.f, sq = 0.f;
#pragma unroll
        for (int j = 0; j < 8; j++) { sum += s[j]; sq = fmaf(s[j], s[j], sq); }
        sum = wredsum(sum);
        sq = wredsum(sq);
        float mean = sum * (1.f / 256.f);
        float var = sq * (1.f / 256.f) - mean * mean;
        float rstd = rsqrtf(var + EPS_LN);

        float acc = 0.f;
#pragma unroll
        for (int j = 0; j < 8; j++) {
            float u = fmaf((s[j] - mean) * rstd, ga[j], ba[j]);
            // inline fast exact-GELU, 0.5 folded into hw
            float z = 0.70710678118654752f * u;
            float az = fabsf(z);
            float t = __fdividef(1.0f, fmaf(0.3275911f, az, 1.0f));
            float poly = t * fmaf(t, fmaf(t, fmaf(t, fmaf(t, 1.061405429f, -1.453152027f),
                                                  1.421413741f),
                                          -0.284496736f),
                                  0.254829592f);
            float ee = __expf(-az * az);
            float erf_z = copysignf(fmaf(-poly, ee, 1.0f), z);
            acc = fmaf(u * (1.0f + erf_z), hw[j], acc);
        }
        acc = wredsum(acc);
        if (lane == 0) out[e] = acc + b2;
    }
}

// ============================================================================
// K3: fr branch  x[64] -> Linear(128) -> LN -> GELU -> Linear(64)
// ============================================================================
__global__ __launch_bounds__(64) void k_fr(const float* __restrict__ x,
                                           const float* __restrict__ w1,  // [64,128]
                                           const float* __restrict__ b1,
                                           const float* __restrict__ gm,
                                           const float* __restrict__ bt,
                                           const float* __restrict__ w2,  // [128,64]
                                           const float* __restrict__ b2,
                                           float* __restrict__ out, int N) {
    __shared__ float xs[16][64];
    __shared__ float hs[16][128];
    const int t = threadIdx.x;
    const int n0 = blockIdx.x * 16;

    {
        float4* xs4 = reinterpret_cast<float4*>(&xs[0][0]);
        const float4* x4 = reinterpret_cast<const float4*>(x);
#pragma unroll
        for (int i = t; i < 256; i += 64) {
            int node = n0 + (i >> 4);
            float4 v = make_float4(0.f, 0.f, 0.f, 0.f);
            if (node < N) v = x4[(size_t)node * 16 + (i & 15)];
            xs4[i] = v;
        }
    }
    __syncthreads();

    // GEMM1: 2 cols/thread
    float a0[16], a1[16];
#pragma unroll
    for (int m = 0; m < 16; m++) { a0[m] = 0.f; a1[m] = 0.f; }
    const int c0 = t, c1 = t + 64;
#pragma unroll 2
    for (int k4 = 0; k4 < 16; k4++) {
        float wr0[4], wr1[4];
#pragma unroll
        for (int j = 0; j < 4; j++) {
            int k = k4 * 4 + j;
            wr0[j] = w1[k * 128 + c0];
            wr1[j] = w1[k * 128 + c1];
        }
#pragma unroll
        for (int m = 0; m < 16; m++) {
            float4 xv = *reinterpret_cast<const float4*>(&xs[m][k4 * 4]);
            float xa[4] = {xv.x, xv.y, xv.z, xv.w};
#pragma unroll
            for (int j = 0; j < 4; j++) {
                a0[m] = fmaf(xa[j], wr0[j], a0[m]);
                a1[m] = fmaf(xa[j], wr1[j], a1[m]);
            }
        }
    }
    {
        float bb0 = b1[c0], bb1 = b1[c1];
#pragma unroll
        for (int m = 0; m < 16; m++) { hs[m][c0] = a0[m] + bb0; hs[m][c1] = a1[m] + bb1; }
    }
    __syncthreads();

    // LN + GELU (2 warps x 8 nodes), 4 elems/lane
    {
        const int warp = t >> 5, lane = t & 31;
        float rg[4], rb[4];
#pragma unroll
        for (int q = 0; q < 4; q++) { rg[q] = gm[lane + 32 * q]; rb[q] = bt[lane + 32 * q]; }
        for (int mm = 0; mm < 8; mm++) {
            int m = warp * 8 + mm;
            float v[4];
            float sum = 0.f, sq = 0.f;
#pragma unroll
            for (int q = 0; q < 4; q++) {
                v[q] = hs[m][lane + 32 * q];
                sum += v[q];
                sq = fmaf(v[q], v[q], sq);
            }
            sum = wredsum(sum);
            sq = wredsum(sq);
            float mean = sum * (1.f / 128.f);
            float var = sq * (1.f / 128.f) - mean * mean;
            float rstd = rsqrtf(var + EPS_LN);
#pragma unroll
            for (int q = 0; q < 4; q++) {
                float u = fmaf((v[q] - mean) * rstd, rg[q], rb[q]);
                hs[m][lane + 32 * q] = gelu_fast(u);
            }
        }
    }
    __syncthreads();

    // GEMM2: thread = (mgroup, 2 outputs)
    {
        const int mg = t >> 5;
        const int o0 = (t & 31) * 2;
        float acc[8][2];
#pragma unroll
        for (int mm = 0; mm < 8; mm++) { acc[mm][0] = 0.f; acc[mm][1] = 0.f; }
#pragma unroll 2
        for (int j4 = 0; j4 < 32; j4++) {
            float2 wv[4];
#pragma unroll
            for (int j = 0; j < 4; j++)
                wv[j] = *reinterpret_cast<const float2*>(&w2[(j4 * 4 + j) * 64 + o0]);
#pragma unroll
            for (int mm = 0; mm < 8; mm++) {
                int m = mg * 8 + mm;
                float4 gv = *reinterpret_cast<const float4*>(&hs[m][j4 * 4]);
                acc[mm][0] = fmaf(gv.x, wv[0].x, acc[mm][0]);
                acc[mm][0] = fmaf(gv.y, wv[1].x, acc[mm][0]);
                acc[mm][0] = fmaf(gv.z, wv[2].x, acc[mm][0]);
                acc[mm][0] = fmaf(gv.w, wv[3].x, acc[mm][0]);
                acc[mm][1] = fmaf(gv.x, wv[0].y, acc[mm][1]);
                acc[mm][1] = fmaf(gv.y, wv[1].y, acc[mm][1]);
                acc[mm][1] = fmaf(gv.z, wv[2].y, acc[mm][1]);
                acc[mm][1] = fmaf(gv.w, wv[3].y, acc[mm][1]);
            }
        }
        float bo0 = b2[o0], bo1 = b2[o0 + 1];
#pragma unroll
        for (int mm = 0; mm < 8; mm++) {
            int n = n0 + mg * 8 + mm;
            if (n < N) {
                out[(size_t)n * 64 + o0] = acc[mm][0] + bo0;
                out[(size_t)n * 64 + o0 + 1] = acc[mm][1] + bo1;
            }
        }
    }
}

// ============================================================================
// K4: ph branch  x[64] -> Linear(256) -> LN -> GELU -> Linear(128)
// ============================================================================
__global__ __launch_bounds__(64) void k_ph(const float* __restrict__ x,
                                           const float* __restrict__ w1,  // [64,256]
                                           const float* __restrict__ b1,
                                           const float* __restrict__ gm,
                                           const float* __restrict__ bt,
                                           const float* __restrict__ w2,  // [256,128]
                                           const float* __restrict__ b2,
                                           float* __restrict__ out, int N) {
    __shared__ float xs[16][64];
    __shared__ float hs[16][256];
    const int t = threadIdx.x;
    const int n0 = blockIdx.x * 16;

    {
        float4* xs4 = reinterpret_cast<float4*>(&xs[0][0]);
        const float4* x4 = reinterpret_cast<const float4*>(x);
#pragma unroll
        for (int i = t; i < 256; i += 64) {
            int node = n0 + (i >> 4);
            float4 v = make_float4(0.f, 0.f, 0.f, 0.f);
            if (node < N) v = x4[(size_t)node * 16 + (i & 15)];
            xs4[i] = v;
        }
    }
    __syncthreads();

    // GEMM1: 4 cols/thread (cols t, t+64, t+128, t+192)
    float a[4][16];
#pragma unroll
    for (int cc = 0; cc < 4; cc++)
#pragma unroll
        for (int m = 0; m < 16; m++) a[cc][m] = 0.f;

#pragma unroll 2
    for (int k4 = 0; k4 < 16; k4++) {
        float wr[4][4];
#pragma unroll
        for (int cc = 0; cc < 4; cc++)
#pragma unroll
            for (int j = 0; j < 4; j++)
                wr[cc][j] = w1[(k4 * 4 + j) * 256 + t + 64 * cc];
#pragma unroll
        for (int m = 0; m < 16; m++) {
            float4 xv = *reinterpret_cast<const float4*>(&xs[m][k4 * 4]);
            float xa[4] = {xv.x, xv.y, xv.z, xv.w};
#pragma unroll
            for (int cc = 0; cc < 4; cc++)
#pragma unroll
                for (int j = 0; j < 4; j++)
                    a[cc][m] = fmaf(xa[j], wr[cc][j], a[cc][m]);
        }
    }
#pragma unroll
    for (int cc = 0; cc < 4; cc++) {
        float bb = b1[t + 64 * cc];
#pragma unroll
        for (int m = 0; m < 16; m++) hs[m][t + 64 * cc] = a[cc][m] + bb;
    }
    __syncthreads();

    // LN + GELU: 8 elems/lane
    {
        const int warp = t >> 5, lane = t & 31;
        float rg[8], rb[8];
#pragma unroll
        for (int q = 0; q < 8; q++) { rg[q] = gm[lane + 32 * q]; rb[q] = bt[lane + 32 * q]; }
        for (int mm = 0; mm < 8; mm++) {
            int m = warp * 8 + mm;
            float v[8];
            float sum = 0.f, sq = 0.f;
#pragma unroll
            for (int q = 0; q < 8; q++) {
                v[q] = hs[m][lane + 32 * q];
                sum += v[q];
                sq = fmaf(v[q], v[q], sq);
            }
            sum = wredsum(sum);
            sq = wredsum(sq);
            float mean = sum * (1.f / 256.f);
            float var = sq * (1.f / 256.f) - mean * mean;
            float rstd = rsqrtf(var + EPS_LN);
#pragma unroll
            for (int q = 0; q < 8; q++) {
                float u = fmaf((v[q] - mean) * rstd, rg[q], rb[q]);
                hs[m][lane + 32 * q] = gelu_fast(u);
            }
        }
    }
    __syncthreads();

    // GEMM2: OUT=128, thread = (mgroup, 4 outputs)
    {
        const int mg = t >> 5;
        const int o0 = (t & 31) * 4;
        float acc[8][4];
#pragma unroll
        for (int mm = 0; mm < 8; mm++)
#pragma unroll
            for (int oo = 0; oo < 4; oo++) acc[mm][oo] = 0.f;

#pragma unroll 2
        for (int j4 = 0; j4 < 64; j4++) {
            float4 wv[4];
#pragma unroll
            for (int j = 0; j < 4; j++)
                wv[j] = *reinterpret_cast<const float4*>(&w2[(j4 * 4 + j) * 128 + o0]);
#pragma unroll
            for (int mm = 0; mm < 8; mm++) {
                int m = mg * 8 + mm;
                float4 gv = *reinterpret_cast<const float4*>(&hs[m][j4 * 4]);
                float gvals[4] = {gv.x, gv.y, gv.z, gv.w};
#pragma unroll
                for (int j = 0; j < 4; j++) {
                    acc[mm][0] = fmaf(gvals[j], wv[j].x, acc[mm][0]);
                    acc[mm][1] = fmaf(gvals[j], wv[j].y, acc[mm][1]);
                    acc[mm][2] = fmaf(gvals[j], wv[j].z, acc[mm][2]);
                    acc[mm][3] = fmaf(gvals[j], wv[j].w, acc[mm][3]);
                }
            }
        }
        float4 bo = *reinterpret_cast<const float4*>(&b2[o0]);
#pragma unroll
        for (int mm = 0; mm < 8; mm++) {
            int n = n0 + mg * 8 + mm;
            if (n < N) {
                float4 r;
                r.x = acc[mm][0] + bo.x;
                r.y = acc[mm][1] + bo.y;
                r.z = acc[mm][2] + bo.z;
                r.w = acc[mm][3] + bo.w;
                *reinterpret_cast<float4*>(&out[(size_t)n * 128 + o0]) = r;
            }
        }
    }
}

// ============================================================================
// launch
// ============================================================================
extern "C" void kernel_launch(void* const* d_in, const int* in_sizes, int n_in,
                              void* d_out, int out_size) {
    const float* x = (const float*)d_in[0];
    const int* ei = (const int*)d_in[1];
    const float* sp_w1 = (const float*)d_in[2];
    const float* sp_b1 = (const float*)d_in[3];
    const float* sp_g = (const float*)d_in[4];
    const float* sp_be = (const float*)d_in[5];
    const float* sp_w2 = (const float*)d_in[6];
    const float* sp_b2 = (const float*)d_in[7];
    const float* fr_w1 = (const float*)d_in[8];
    const float* fr_b1 = (const float*)d_in[9];
    const float* fr_g = (const float*)d_in[10];
    const float* fr_be = (const float*)d_in[11];
    const float* fr_w2 = (const float*)d_in[12];
    const float* fr_b2 = (const float*)d_in[13];
    const float* ph_w1 = (const float*)d_in[14];
    const float* ph_b1 = (const float*)d_in[15];
    const float* ph_g = (const float*)d_in[16];
    const float* ph_be = (const float*)d_in[17];
    const float* ph_w2 = (const float*)d_in[18];
    const float* ph_b2 = (const float*)d_in[19];

    const int N = in_sizes[0] / 64;
    const int E = in_sizes[1] / 2;

    float* out_sp = (float*)d_out;             // [E]
    float* out_fr = out_sp + (size_t)E;        // [N,64]
    float* out_ph = out_fr + (size_t)N * 64;   // [N,128]

    int nblk = (N + 15) / 16;
    k_pq<<<nblk, 128>>>(x, sp_w1, sp_b1, N);
    k_fr<<<nblk, 64>>>(x, fr_w1, fr_b1, fr_g, fr_be, fr_w2, fr_b2, out_fr, N);
    k_ph<<<nblk, 64>>>(x, ph_w1, ph_b1, ph_g, ph_be, ph_w2, ph_b2, out_ph, N);

    long warps = ((long)E + EPW - 1) / EPW;
    int eblocks = (int)((warps + 7) / 8);
    k_edge<<<eblocks, 256>>>(ei, E, sp_g, sp_be, sp_w2, sp_b2, out_sp);
}